// round 9
// baseline (speedup 1.0000x reference)
#include <cuda_runtime.h>
#include <cstdint>
#include <math.h>

// ==================== scratch (no allocations allowed) ====================
__device__ float g_pooled[16 * 64];               // [b][c]
__device__ float g_att[16 * 4];                   // [b][k]
__device__ float g_aggb[16 * 64];                 // [b][o]
// fragment layout: [b][tap][r][o][2], r=(c>>3)*4+(c&3) holds (w[o][c_lo], w[o][c_lo+4]),
// c_lo=(r>>2)*8+(r&3); tf32-rounded. One tap = 32 rows = 4096 contiguous floats.
__device__ float g_aggwt2[16 * 9 * 32 * 64 * 2];

// ==================== helpers ====================
__device__ __forceinline__ uint32_t f2tf32(float f) {
    uint32_t u;
    asm("cvt.rna.tf32.f32 %0, %1;" : "=r"(u) : "f"(f));
    return u;
}
__device__ __forceinline__ uint32_t smem_u32(const void* p) {
    uint32_t a;
    asm("{ .reg .u64 t; cvta.to.shared.u64 t, %1; cvt.u32.u64 %0, t; }" : "=r"(a) : "l"(p));
    return a;
}
__device__ __forceinline__ void cp_async16(uint32_t dst, const float* src) {
    asm volatile("cp.async.cg.shared.global [%0], [%1], 16;" :: "r"(dst), "l"(src));
}
__device__ __forceinline__ void cp_async16z(uint32_t dst, const float* src, uint32_t sz) {
    asm volatile("cp.async.cg.shared.global [%0], [%1], 16, %2;" :: "r"(dst), "l"(src), "r"(sz));
}
#define CP_COMMIT() asm volatile("cp.async.commit_group;" ::: "memory")
#define CP_WAIT0()  asm volatile("cp.async.wait_group 0;" ::: "memory")

__device__ __forceinline__ void mma_tf32(float& c0, float& c1, float& c2, float& c3,
                                         uint32_t a0, uint32_t a1, uint32_t a2, uint32_t a3,
                                         uint32_t b0, uint32_t b1) {
    asm volatile(
        "mma.sync.aligned.m16n8k8.row.col.f32.tf32.tf32.f32 "
        "{%0,%1,%2,%3}, {%4,%5,%6,%7}, {%8,%9}, {%0,%1,%2,%3};"
        : "+f"(c0), "+f"(c1), "+f"(c2), "+f"(c3)
        : "r"(a0), "r"(a1), "r"(a2), "r"(a3), "r"(b0), "r"(b1));
}

// ==================== kernel 1: global average pool ====================
__global__ void pool_kernel(const float* __restrict__ x) {
    const int plane = blockIdx.x;               // b*64 + c
    const float4* p = (const float4*)(x + (size_t)plane * 65536);
    float s = 0.f;
    for (int i = threadIdx.x; i < 16384; i += 256) {
        float4 v = p[i];
        s += (v.x + v.y) + (v.z + v.w);
    }
    #pragma unroll
    for (int off = 16; off > 0; off >>= 1)
        s += __shfl_xor_sync(0xFFFFFFFFu, s, off);
    __shared__ float sm[8];
    const int lane = threadIdx.x & 31, wid = threadIdx.x >> 5;
    if (lane == 0) sm[wid] = s;
    __syncthreads();
    if (threadIdx.x == 0) {
        float t = 0.f;
        #pragma unroll
        for (int w = 0; w < 8; w++) t += sm[w];
        g_pooled[plane] = t * (1.0f / 65536.0f);
    }
}

// ==================== kernel 2: attention + aggregated bias (1 block / b) ====
__global__ void attn_kernel(const float* __restrict__ fc1_w, const float* __restrict__ fc2_w,
                            const float* __restrict__ fc2_b, const float* __restrict__ bias_k) {
    __shared__ float sh[17];
    __shared__ float sl[4];
    const int b = blockIdx.x;
    const int t = threadIdx.x;
    if (t < 17) {
        float s = 0.f;
        #pragma unroll
        for (int c = 0; c < 64; c++) s += g_pooled[b * 64 + c] * fc1_w[t * 64 + c];
        sh[t] = (s >= 0.f) ? s : 0.2f * s;
    }
    __syncthreads();
    if (t < 4) {
        float s = fc2_b[t];
        #pragma unroll
        for (int j = 0; j < 17; j++) s += sh[j] * fc2_w[t * 17 + j];
        sl[t] = s * (1.0f / 34.0f);
    }
    __syncthreads();
    if (t == 0) {
        float m = fmaxf(fmaxf(sl[0], sl[1]), fmaxf(sl[2], sl[3]));
        float e0 = expf(sl[0] - m), e1 = expf(sl[1] - m);
        float e2 = expf(sl[2] - m), e3 = expf(sl[3] - m);
        float inv = 1.0f / (e0 + e1 + e2 + e3);
        sl[0] = e0 * inv; sl[1] = e1 * inv; sl[2] = e2 * inv; sl[3] = e3 * inv;
    }
    __syncthreads();
    if (t < 4) g_att[b * 4 + t] = sl[t];
    if (t < 64) {
        float s = 0.f;
        #pragma unroll
        for (int k = 0; k < 4; k++) s += sl[k] * bias_k[k * 64 + t];
        g_aggb[b * 64 + t] = s;
    }
}

// ==================== kernel 3: aggregate weights -> fragment layout ====
__global__ void aggw_kernel(const float* __restrict__ weight) {  // [4,64,64,3,3]
    const int idx = blockIdx.x * 256 + threadIdx.x;   // b*4096 + o*64 + c
    const int b  = idx >> 12;
    const int oc = idx & 4095;
    const int o  = oc >> 6, c = oc & 63;
    const int r    = ((c >> 3) << 2) + (c & 3);
    const int half = (c >> 2) & 1;
    const float a0 = g_att[b * 4 + 0], a1 = g_att[b * 4 + 1];
    const float a2 = g_att[b * 4 + 2], a3 = g_att[b * 4 + 3];
    const float* w0 = weight + (size_t)oc * 9;
    #pragma unroll
    for (int tap = 0; tap < 9; tap++) {
        float s = a0 * w0[tap]
                + a1 * w0[4096 * 9 + tap]
                + a2 * w0[2 * 4096 * 9 + tap]
                + a3 * w0[3 * 4096 * 9 + tap];
        g_aggwt2[((((size_t)(b * 9 + tap) * 32) + r) * 64 + o) * 2 + half] =
            __uint_as_float(f2tf32(s));
    }
}

// ==================== kernel 4: conv, tf32 mma.sync, 9 steps of K=64 ====
// CTA = (y, b): full 256-wide output row, n = 64. 128 threads / 4 warps,
// warp tile 64x64. 9 steps = 9 taps; K = 64 channels per step.
// s_A (single): 64 channel rows x A_STR(264). Interior gx at col gx+4, halo
//   cols 3 / 260. Restaged at dy boundaries (2x), after a full-CTA sync.
// s_B (double): 32 fragment rows x 136 per tap; cp.async straight copy,
//   issued one tap ahead, before the MMA burst.
#define A_STR 264
#define B_STR 136
#define SMEM_FLOATS (64 * A_STR + 2 * 32 * B_STR + 64)

__global__ __launch_bounds__(128, 2)
void conv_kernel(const float* __restrict__ x, float* __restrict__ out) {
    extern __shared__ float smem[];
    float* s_A    = smem;                           // 64*264
    float* s_B    = smem + 64 * A_STR;              // 2 * 32*136
    float* s_bias = s_B + 2 * 32 * B_STR;           // 64

    const int y    = blockIdx.x;
    const int b    = blockIdx.y;
    const int t    = threadIdx.x;
    const int lane = t & 31, w = t >> 5;
    const int g    = lane >> 2, tig = lane & 3;

    if (t < 64) s_bias[t] = g_aggb[b * 64 + t];

    float acc[4][8][4];
    #pragma unroll
    for (int mt = 0; mt < 4; mt++)
        #pragma unroll
        for (int nt = 0; nt < 8; nt++)
            #pragma unroll
            for (int r = 0; r < 4; r++) acc[mt][nt][r] = 0.f;

    const float* xb    = x + ((size_t)b << 22);
    const float* wtapb = g_aggwt2 + (size_t)(b * 9) * 4096;
    const uint32_t sA_addr = smem_u32(s_A);
    const uint32_t sB_addr = smem_u32(s_B);

    // ---- A stage for dy group dyi (all 64 channels of input row y+dyi-1) ----
    auto issueA = [&](int dyi) {
        const int gy  = y + dyi - 1;
        const bool oky = (unsigned)gy < 256u;
        const int gyc = oky ? gy : 0;
        const uint32_t sz = oky ? 16u : 0u;
        const float* srcb = xb + (size_t)gyc * 256;
        #pragma unroll
        for (int j = 0; j < 32; j++) {
            const int i   = j * 128 + t;            // 0..4095
            const int cc  = i >> 6, k16 = i & 63;
            cp_async16z(sA_addr + (uint32_t)(cc * (A_STR * 4) + 16 + k16 * 16),
                        srcb + ((size_t)cc << 16) + k16 * 4, sz);
        }
        {                                           // halo: 2 floats per channel
            const int cc = t >> 1, side = t & 1;
            const int gx = side ? 256 : -1;
            float v = 0.f;
            if (oky && (unsigned)gx < 256u)
                v = __ldg(xb + ((size_t)cc << 16) + (size_t)gy * 256 + gx);
            s_A[cc * A_STR + (side ? 260 : 3)] = v;
        }
    };

    // ---- B stage for tap (32 fragment rows, contiguous copy) ----
    auto issueB = [&](int tap) {
        const float* src = wtapb + (size_t)tap * 4096;
        const uint32_t dstb = sB_addr + (uint32_t)((tap & 1) * 32 * B_STR * 4);
        #pragma unroll
        for (int j = 0; j < 8; j++) {
            const int i = j * 128 + t;              // 0..1023
            const int r = i >> 5, k16 = i & 31;
            cp_async16(dstb + (uint32_t)(r * (B_STR * 4) + k16 * 16), src + i * 4);
        }
    };

    // prologue
    issueA(0);
    issueB(0);
    CP_COMMIT();

    #pragma unroll 1
    for (int s = 0; s < 9; s++) {
        const int dyi = s / 3;
        const int dx  = (s - dyi * 3) - 1;

        CP_WAIT0();            // A(dyi) + B(s) resident
        __syncthreads();

        // next B always issued before the burst (idle buffer)
        if (s < 8) {
            issueB(s + 1);
            CP_COMMIT();
        }

        const float* sBb = s_B + (s & 1) * (32 * B_STR);
        const int colbase = w * 64 + g + dx + 4;

        #pragma unroll
        for (int ks = 0; ks < 8; ks++) {
            const float* aRow0 = s_A + (ks * 8 + tig) * A_STR + colbase;
            const float* aRow4 = aRow0 + 4 * A_STR;
            uint32_t a[4][4];
            #pragma unroll
            for (int mt = 0; mt < 4; mt++) {
                a[mt][0] = __float_as_uint(aRow0[mt * 16]);
                a[mt][1] = __float_as_uint(aRow0[mt * 16 + 8]);
                a[mt][2] = __float_as_uint(aRow4[mt * 16]);
                a[mt][3] = __float_as_uint(aRow4[mt * 16 + 8]);
            }
            const float* bRow = sBb + (ks * 4 + tig) * B_STR;
            #pragma unroll
            for (int nt = 0; nt < 8; nt++) {
                float2 bv = *(const float2*)(bRow + 2 * (nt * 8 + g));
                const uint32_t b0 = __float_as_uint(bv.x), b1 = __float_as_uint(bv.y);
                #pragma unroll
                for (int mt = 0; mt < 4; mt++)
                    mma_tf32(acc[mt][nt][0], acc[mt][nt][1], acc[mt][nt][2], acc[mt][nt][3],
                             a[mt][0], a[mt][1], a[mt][2], a[mt][3], b0, b1);
            }
        }

        // dy boundary: restage A after all warps finished reading it
        if (s < 8 && dx == 1) {
            __syncthreads();
            issueA(dyi + 1);
            CP_COMMIT();
        }
    }

    // ---- epilogue ----
    const size_t obase = ((size_t)b << 22) + (size_t)y * 256;
    #pragma unroll
    for (int nt = 0; nt < 8; nt++) {
        const int o0 = nt * 8 + 2 * tig;
        const float bias0 = s_bias[o0], bias1 = s_bias[o0 + 1];
        #pragma unroll
        for (int mt = 0; mt < 4; mt++) {
            const int m = w * 64 + mt * 16 + g;
            float* p0 = out + obase + ((size_t)o0 << 16) + m;
            float* p1 = out + obase + ((size_t)(o0 + 1) << 16) + m;
            p0[0] = acc[mt][nt][0] + bias0;
            p1[0] = acc[mt][nt][1] + bias1;
            p0[8] = acc[mt][nt][2] + bias0;
            p1[8] = acc[mt][nt][3] + bias1;
        }
    }
}

// ==================== launcher ====================
extern "C" void kernel_launch(void* const* d_in, const int* in_sizes, int n_in,
                              void* d_out, int out_size) {
    const float* x      = (const float*)d_in[0];  // [16,64,256,256]
    const float* fc1_w  = (const float*)d_in[1];  // [17,64]
    const float* fc2_w  = (const float*)d_in[2];  // [4,17]
    const float* fc2_b  = (const float*)d_in[3];  // [4]
    const float* weight = (const float*)d_in[4];  // [4,64,64,3,3]
    const float* bias_k = (const float*)d_in[5];  // [4,64]
    float* out = (float*)d_out;

    const int smem_bytes = SMEM_FLOATS * 4;
    cudaFuncSetAttribute(conv_kernel, cudaFuncAttributeMaxDynamicSharedMemorySize, smem_bytes);

    pool_kernel<<<1024, 256>>>(x);
    attn_kernel<<<16, 64>>>(fc1_w, fc2_w, fc2_b, bias_k);
    aggw_kernel<<<256, 256>>>(weight);
    conv_kernel<<<dim3(256, 16), 128, smem_bytes>>>(x, out);
}

// round 10
// speedup vs baseline: 1.1414x; 1.1414x over previous
#include <cuda_runtime.h>
#include <cstdint>
#include <math.h>

// ==================== scratch (no allocations allowed) ====================
__device__ float g_pooled[16 * 64];               // [b][c]
__device__ float g_att[16 * 4];                   // [b][k]
__device__ float g_aggb[16 * 64];                 // [b][o]
// fragment layout: [b][tap][r][o][2], r=(c>>3)*4+(c&3) holds (w[o][c_lo], w[o][c_lo+4]),
// c_lo=(r>>2)*8+(r&3); tf32-rounded.
__device__ float g_aggwt2[16 * 9 * 32 * 64 * 2];

// ==================== helpers ====================
__device__ __forceinline__ uint32_t f2tf32(float f) {
    uint32_t u;
    asm("cvt.rna.tf32.f32 %0, %1;" : "=r"(u) : "f"(f));
    return u;
}
__device__ __forceinline__ uint32_t smem_u32(const void* p) {
    uint32_t a;
    asm("{ .reg .u64 t; cvta.to.shared.u64 t, %1; cvt.u32.u64 %0, t; }" : "=r"(a) : "l"(p));
    return a;
}
__device__ __forceinline__ void cp_async16(uint32_t dst, const float* src) {
    asm volatile("cp.async.ca.shared.global [%0], [%1], 16;" :: "r"(dst), "l"(src));
}
__device__ __forceinline__ void cp_async16z(uint32_t dst, const float* src, uint32_t sz) {
    asm volatile("cp.async.ca.shared.global [%0], [%1], 16, %2;" :: "r"(dst), "l"(src), "r"(sz));
}
__device__ __forceinline__ void cp_async4z(uint32_t dst, const float* src, uint32_t sz) {
    asm volatile("cp.async.ca.shared.global [%0], [%1], 4, %2;" :: "r"(dst), "l"(src), "r"(sz));
}
#define CP_COMMIT() asm volatile("cp.async.commit_group;" ::: "memory")
#define CP_WAIT0()  asm volatile("cp.async.wait_group 0;" ::: "memory")
#define CP_WAIT1()  asm volatile("cp.async.wait_group 1;" ::: "memory")

__device__ __forceinline__ void mma_tf32(float& c0, float& c1, float& c2, float& c3,
                                         uint32_t a0, uint32_t a1, uint32_t a2, uint32_t a3,
                                         uint32_t b0, uint32_t b1) {
    asm volatile(
        "mma.sync.aligned.m16n8k8.row.col.f32.tf32.tf32.f32 "
        "{%0,%1,%2,%3}, {%4,%5,%6,%7}, {%8,%9}, {%0,%1,%2,%3};"
        : "+f"(c0), "+f"(c1), "+f"(c2), "+f"(c3)
        : "r"(a0), "r"(a1), "r"(a2), "r"(a3), "r"(b0), "r"(b1));
}

// ==================== kernel 1: global average pool ====================
__global__ void pool_kernel(const float* __restrict__ x) {
    const int plane = blockIdx.x;               // b*64 + c
    const float4* p = (const float4*)(x + (size_t)plane * 65536);
    float s = 0.f;
    for (int i = threadIdx.x; i < 16384; i += 256) {
        float4 v = p[i];
        s += (v.x + v.y) + (v.z + v.w);
    }
    #pragma unroll
    for (int off = 16; off > 0; off >>= 1)
        s += __shfl_xor_sync(0xFFFFFFFFu, s, off);
    __shared__ float sm[8];
    const int lane = threadIdx.x & 31, wid = threadIdx.x >> 5;
    if (lane == 0) sm[wid] = s;
    __syncthreads();
    if (threadIdx.x == 0) {
        float t = 0.f;
        #pragma unroll
        for (int w = 0; w < 8; w++) t += sm[w];
        g_pooled[plane] = t * (1.0f / 65536.0f);
    }
}

// ==================== kernel 2: attention + aggregated bias (1 block / b) ====
__global__ void attn_kernel(const float* __restrict__ fc1_w, const float* __restrict__ fc2_w,
                            const float* __restrict__ fc2_b, const float* __restrict__ bias_k) {
    __shared__ float sh[17];
    __shared__ float sl[4];
    const int b = blockIdx.x;
    const int t = threadIdx.x;
    if (t < 17) {
        float s = 0.f;
        #pragma unroll
        for (int c = 0; c < 64; c++) s += g_pooled[b * 64 + c] * fc1_w[t * 64 + c];
        sh[t] = (s >= 0.f) ? s : 0.2f * s;
    }
    __syncthreads();
    if (t < 4) {
        float s = fc2_b[t];
        #pragma unroll
        for (int j = 0; j < 17; j++) s += sh[j] * fc2_w[t * 17 + j];
        sl[t] = s * (1.0f / 34.0f);
    }
    __syncthreads();
    if (t == 0) {
        float m = fmaxf(fmaxf(sl[0], sl[1]), fmaxf(sl[2], sl[3]));
        float e0 = expf(sl[0] - m), e1 = expf(sl[1] - m);
        float e2 = expf(sl[2] - m), e3 = expf(sl[3] - m);
        float inv = 1.0f / (e0 + e1 + e2 + e3);
        sl[0] = e0 * inv; sl[1] = e1 * inv; sl[2] = e2 * inv; sl[3] = e3 * inv;
    }
    __syncthreads();
    if (t < 4) g_att[b * 4 + t] = sl[t];
    if (t < 64) {
        float s = 0.f;
        #pragma unroll
        for (int k = 0; k < 4; k++) s += sl[k] * bias_k[k * 64 + t];
        g_aggb[b * 64 + t] = s;
    }
}

// ==================== kernel 3: aggregate weights -> fragment layout ====
__global__ void aggw_kernel(const float* __restrict__ weight) {  // [4,64,64,3,3]
    const int idx = blockIdx.x * 256 + threadIdx.x;   // b*4096 + o*64 + c
    const int b  = idx >> 12;
    const int oc = idx & 4095;
    const int o  = oc >> 6, c = oc & 63;
    const int r    = ((c >> 3) << 2) + (c & 3);
    const int half = (c >> 2) & 1;
    const float a0 = g_att[b * 4 + 0], a1 = g_att[b * 4 + 1];
    const float a2 = g_att[b * 4 + 2], a3 = g_att[b * 4 + 3];
    const float* w0 = weight + (size_t)oc * 9;
    #pragma unroll
    for (int tap = 0; tap < 9; tap++) {
        float s = a0 * w0[tap]
                + a1 * w0[4096 * 9 + tap]
                + a2 * w0[2 * 4096 * 9 + tap]
                + a3 * w0[3 * 4096 * 9 + tap];
        g_aggwt2[((((size_t)(b * 9 + tap) * 32) + r) * 64 + o) * 2 + half] =
            __uint_as_float(f2tf32(s));
    }
}

// ==================== kernel 4: conv, tf32 mma.sync, fully pipelined ====
// CTA = (y, b): full 256-wide output row, n = 64. 128 threads / 4 warps,
// warp tile 64x64. 18 steps = 6 groups (dy, ch-half) x 3 dx.
// s_A double buffer [2][32 c][A_STR]: interior gx at col gx+4, halo cols 3 / 260.
// Commit discipline: B(s+1) is always its own commit group, issued before the
// burst. A(g+1) is a SEPARATE group committed after B at dxi==0 steps; the
// dxi==1 step uses wait_group 1 (FIFO completes B, leaves A pending) so the
// 33KB A copy gets ~2 full MMA bursts to land. Halo is cp.async too.
#define A_STR 264
#define B_STR 136
#define SMEM_FLOATS (2 * 32 * A_STR + 2 * 16 * B_STR + 64)

__global__ __launch_bounds__(128, 2)
void conv_kernel(const float* __restrict__ x, float* __restrict__ out) {
    extern __shared__ float smem[];
    float* s_A    = smem;                           // 2 * 32*264
    float* s_B    = smem + 2 * 32 * A_STR;          // 2 * 16*136
    float* s_bias = s_B + 2 * 16 * B_STR;           // 64

    const int y    = blockIdx.x;
    const int b    = blockIdx.y;
    const int t    = threadIdx.x;
    const int lane = t & 31, w = t >> 5;
    const int g    = lane >> 2, tig = lane & 3;

    if (t < 64) s_bias[t] = g_aggb[b * 64 + t];

    float acc[4][8][4];
    #pragma unroll
    for (int mt = 0; mt < 4; mt++)
        #pragma unroll
        for (int nt = 0; nt < 8; nt++)
            #pragma unroll
            for (int r = 0; r < 4; r++) acc[mt][nt][r] = 0.f;

    const float* xb    = x + ((size_t)b << 22);
    const float* wtapb = g_aggwt2 + (size_t)(b * 9) * 4096;
    const uint32_t sA_addr = smem_u32(s_A);
    const uint32_t sB_addr = smem_u32(s_B);

    // ---- A stage for group = dyi*2 + ch (buffer = group&1); all cp.async ----
    auto issueA = [&](int group) {
        const int dyi = group >> 1;
        const int ch  = group & 1;
        const int gy  = y + dyi - 1;
        const bool oky = (unsigned)gy < 256u;
        const int gyc = oky ? gy : 0;
        const uint32_t sz = oky ? 16u : 0u;
        const uint32_t dstA = sA_addr + (uint32_t)((group & 1) * 32 * A_STR * 4);
        const float* srcb = xb + ((size_t)(ch << 5) << 16) + (size_t)gyc * 256;
        #pragma unroll
        for (int j = 0; j < 16; j++) {
            const int i   = j * 128 + t;            // 0..2047
            const int cc  = i >> 6, k16 = i & 63;
            cp_async16z(dstA + (uint32_t)(cc * (A_STR * 4) + 16 + k16 * 16),
                        srcb + ((size_t)cc << 16) + k16 * 4, sz);
        }
        if (t < 64) {                               // halo, 1 float per thread x 2 sides
            const int cc = t >> 1, side = t & 1;
            const int gx = side ? 256 : -1;
            const bool okh = oky && (unsigned)gx < 256u;
            cp_async4z(dstA + (uint32_t)((cc * A_STR + (side ? 260 : 3)) * 4),
                       xb + ((size_t)((ch << 5) + cc) << 16) + (size_t)gyc * 256 + (okh ? gx : 0),
                       okh ? 4u : 0u);
        }
    };

    // ---- B stage for step s: (tap, ch-half) fragment rows, contiguous copy ----
    auto issueB = [&](int step) {
        const int gidx = step / 3, dxi = step - gidx * 3;
        const int tap  = (gidx >> 1) * 3 + dxi;
        const int ch   = gidx & 1;
        const float* src = wtapb + (size_t)tap * 4096 + (ch << 11);
        const uint32_t dstb = sB_addr + (uint32_t)((step & 1) * 16 * B_STR * 4);
        #pragma unroll
        for (int j = 0; j < 4; j++) {
            const int i = j * 128 + t;              // 0..511
            const int r = i >> 5, k16 = i & 31;
            cp_async16(dstb + (uint32_t)(r * (B_STR * 4) + k16 * 16), src + i * 4);
        }
    };

    // prologue: A(0) and B(0), single group (both needed at step 0 anyway)
    issueA(0);
    issueB(0);
    CP_COMMIT();

    #pragma unroll 1
    for (int s = 0; s < 18; s++) {
        const int gidx = s / 3;
        const int dxi  = s - gidx * 3;
        const int dx   = dxi - 1;

        // dxi==1: B(s) is the oldest pending group; A(g+1) may stay in flight.
        if (dxi == 1) CP_WAIT1(); else CP_WAIT0();
        __syncthreads();

        // issue next copies BEFORE the MMA burst (targets are idle buffers).
        // B first (own group), then A (own group) so FIFO lets A lag.
        if (s < 17) {
            issueB(s + 1);
            CP_COMMIT();
            if (dxi == 0 && gidx < 5) {
                issueA(gidx + 1);
                CP_COMMIT();
            }
        }

        const float* sAb = s_A + (gidx & 1) * (32 * A_STR);
        const float* sBb = s_B + (s & 1) * (16 * B_STR);
        const int colbase = w * 64 + g + dx + 4;

        #pragma unroll
        for (int ks = 0; ks < 4; ks++) {
            const float* aRow0 = sAb + (ks * 8 + tig) * A_STR + colbase;
            const float* aRow4 = aRow0 + 4 * A_STR;
            uint32_t a[4][4];
            #pragma unroll
            for (int mt = 0; mt < 4; mt++) {
                a[mt][0] = __float_as_uint(aRow0[mt * 16]);
                a[mt][1] = __float_as_uint(aRow0[mt * 16 + 8]);
                a[mt][2] = __float_as_uint(aRow4[mt * 16]);
                a[mt][3] = __float_as_uint(aRow4[mt * 16 + 8]);
            }
            const float* bRow = sBb + (ks * 4 + tig) * B_STR;
            #pragma unroll
            for (int nt = 0; nt < 8; nt++) {
                float2 bv = *(const float2*)(bRow + 2 * (nt * 8 + g));
                const uint32_t b0 = __float_as_uint(bv.x), b1 = __float_as_uint(bv.y);
                #pragma unroll
                for (int mt = 0; mt < 4; mt++)
                    mma_tf32(acc[mt][nt][0], acc[mt][nt][1], acc[mt][nt][2], acc[mt][nt][3],
                             a[mt][0], a[mt][1], a[mt][2], a[mt][3], b0, b1);
            }
        }
    }

    // ---- epilogue ----
    const size_t obase = ((size_t)b << 22) + (size_t)y * 256;
    #pragma unroll
    for (int nt = 0; nt < 8; nt++) {
        const int o0 = nt * 8 + 2 * tig;
        const float bias0 = s_bias[o0], bias1 = s_bias[o0 + 1];
        #pragma unroll
        for (int mt = 0; mt < 4; mt++) {
            const int m = w * 64 + mt * 16 + g;
            float* p0 = out + obase + ((size_t)o0 << 16) + m;
            float* p1 = out + obase + ((size_t)(o0 + 1) << 16) + m;
            p0[0] = acc[mt][nt][0] + bias0;
            p1[0] = acc[mt][nt][1] + bias1;
            p0[8] = acc[mt][nt][2] + bias0;
            p1[8] = acc[mt][nt][3] + bias1;
        }
    }
}

// ==================== launcher ====================
extern "C" void kernel_launch(void* const* d_in, const int* in_sizes, int n_in,
                              void* d_out, int out_size) {
    const float* x      = (const float*)d_in[0];  // [16,64,256,256]
    const float* fc1_w  = (const float*)d_in[1];  // [17,64]
    const float* fc2_w  = (const float*)d_in[2];  // [4,17]
    const float* fc2_b  = (const float*)d_in[3];  // [4]
    const float* weight = (const float*)d_in[4];  // [4,64,64,3,3]
    const float* bias_k = (const float*)d_in[5];  // [4,64]
    float* out = (float*)d_out;

    const int smem_bytes = SMEM_FLOATS * 4;
    cudaFuncSetAttribute(conv_kernel, cudaFuncAttributeMaxDynamicSharedMemorySize, smem_bytes);

    pool_kernel<<<1024, 256>>>(x);
    attn_kernel<<<16, 64>>>(fc1_w, fc2_w, fc2_b, bias_k);
    aggw_kernel<<<256, 256>>>(weight);
    conv_kernel<<<dim3(256, 16), 128, smem_bytes>>>(x, out);
}

// round 11
// speedup vs baseline: 1.7527x; 1.5356x over previous
#include <cuda_runtime.h>
#include <cuda_fp16.h>
#include <cstdint>
#include <math.h>

// ==================== scratch (no allocations allowed) ====================
__device__ float g_pooled[16 * 64];               // [b][c]
__device__ float g_att[16 * 4];                   // [b][k]
__device__ float g_aggb[16 * 64];                 // [b][o]
// x converted to half2 channel pairs: [b][r=c>>1][y][x], u32 = (h(c=2r), h(c=2r+1))
__device__ unsigned g_xh[16 * 32 * 65536];        // 134 MB
// aggregated weights as half2 pairs: [b][tap][p=c>>1][o], u32 = (w[o][2p], w[o][2p+1])
__device__ unsigned g_wh[16 * 9 * 32 * 64];

// ==================== helpers ====================
__device__ __forceinline__ uint32_t smem_u32p(const void* p) {
    uint32_t a;
    asm("{ .reg .u64 t; cvta.to.shared.u64 t, %1; cvt.u32.u64 %0, t; }" : "=r"(a) : "l"(p));
    return a;
}
__device__ __forceinline__ void cp_async16(uint32_t dst, const void* src) {
    asm volatile("cp.async.ca.shared.global [%0], [%1], 16;" :: "r"(dst), "l"(src));
}
__device__ __forceinline__ void cp_async16z(uint32_t dst, const void* src, uint32_t sz) {
    asm volatile("cp.async.ca.shared.global [%0], [%1], 16, %2;" :: "r"(dst), "l"(src), "r"(sz));
}
__device__ __forceinline__ void cp_async4z(uint32_t dst, const void* src, uint32_t sz) {
    asm volatile("cp.async.ca.shared.global [%0], [%1], 4, %2;" :: "r"(dst), "l"(src), "r"(sz));
}
#define CP_COMMIT() asm volatile("cp.async.commit_group;" ::: "memory")
#define CP_WAIT0()  asm volatile("cp.async.wait_group 0;" ::: "memory")
#define CP_WAIT1()  asm volatile("cp.async.wait_group 1;" ::: "memory")

__device__ __forceinline__ void mma_f16(float& c0, float& c1, float& c2, float& c3,
                                        uint32_t a0, uint32_t a1, uint32_t a2, uint32_t a3,
                                        uint32_t b0, uint32_t b1) {
    asm volatile(
        "mma.sync.aligned.m16n8k16.row.col.f32.f16.f16.f32 "
        "{%0,%1,%2,%3}, {%4,%5,%6,%7}, {%8,%9}, {%0,%1,%2,%3};"
        : "+f"(c0), "+f"(c1), "+f"(c2), "+f"(c3)
        : "r"(a0), "r"(a1), "r"(a2), "r"(a3), "r"(b0), "r"(b1));
}
__device__ __forceinline__ unsigned pack_h2(float a, float b) {
    __half2 h = __floats2half2_rn(a, b);          // low = a, high = b
    return *(unsigned*)&h;
}

// ==================== kernel 1: convert x to half2 pairs + global avg pool ====
// block per (b, pair r): reads channels 2r, 2r+1, writes interleaved half2 plane,
// and produces both pooled means.
__global__ void convert_pool_kernel(const float* __restrict__ x) {
    const int br = blockIdx.x;                    // b*32 + r
    const int b  = br >> 5, r = br & 31;
    const float4* p0 = (const float4*)(x + ((size_t)((b << 6) + 2 * r)     << 16));
    const float4* p1 = (const float4*)(x + ((size_t)((b << 6) + 2 * r + 1) << 16));
    uint4* dst = (uint4*)(g_xh + ((size_t)br << 16));
    float s0 = 0.f, s1 = 0.f;
    for (int i = threadIdx.x; i < 16384; i += 256) {
        float4 v0 = p0[i], v1 = p1[i];
        s0 += (v0.x + v0.y) + (v0.z + v0.w);
        s1 += (v1.x + v1.y) + (v1.z + v1.w);
        uint4 o;
        o.x = pack_h2(v0.x, v1.x);
        o.y = pack_h2(v0.y, v1.y);
        o.z = pack_h2(v0.z, v1.z);
        o.w = pack_h2(v0.w, v1.w);
        dst[i] = o;
    }
    #pragma unroll
    for (int off = 16; off > 0; off >>= 1) {
        s0 += __shfl_xor_sync(0xFFFFFFFFu, s0, off);
        s1 += __shfl_xor_sync(0xFFFFFFFFu, s1, off);
    }
    __shared__ float sm0[8], sm1[8];
    const int lane = threadIdx.x & 31, wid = threadIdx.x >> 5;
    if (lane == 0) { sm0[wid] = s0; sm1[wid] = s1; }
    __syncthreads();
    if (threadIdx.x == 0) {
        float t0 = 0.f, t1 = 0.f;
        #pragma unroll
        for (int w = 0; w < 8; w++) { t0 += sm0[w]; t1 += sm1[w]; }
        g_pooled[(b << 6) + 2 * r]     = t0 * (1.0f / 65536.0f);
        g_pooled[(b << 6) + 2 * r + 1] = t1 * (1.0f / 65536.0f);
    }
}

// ==================== kernel 2: attention + aggregated bias (1 block / b) ====
__global__ void attn_kernel(const float* __restrict__ fc1_w, const float* __restrict__ fc2_w,
                            const float* __restrict__ fc2_b, const float* __restrict__ bias_k) {
    __shared__ float sh[17];
    __shared__ float sl[4];
    const int b = blockIdx.x;
    const int t = threadIdx.x;
    if (t < 17) {
        float s = 0.f;
        #pragma unroll
        for (int c = 0; c < 64; c++) s += g_pooled[b * 64 + c] * fc1_w[t * 64 + c];
        sh[t] = (s >= 0.f) ? s : 0.2f * s;
    }
    __syncthreads();
    if (t < 4) {
        float s = fc2_b[t];
        #pragma unroll
        for (int j = 0; j < 17; j++) s += sh[j] * fc2_w[t * 17 + j];
        sl[t] = s * (1.0f / 34.0f);
    }
    __syncthreads();
    if (t == 0) {
        float m = fmaxf(fmaxf(sl[0], sl[1]), fmaxf(sl[2], sl[3]));
        float e0 = expf(sl[0] - m), e1 = expf(sl[1] - m);
        float e2 = expf(sl[2] - m), e3 = expf(sl[3] - m);
        float inv = 1.0f / (e0 + e1 + e2 + e3);
        sl[0] = e0 * inv; sl[1] = e1 * inv; sl[2] = e2 * inv; sl[3] = e3 * inv;
    }
    __syncthreads();
    if (t < 4) g_att[b * 4 + t] = sl[t];
    if (t < 64) {
        float s = 0.f;
        #pragma unroll
        for (int k = 0; k < 4; k++) s += sl[k] * bias_k[k * 64 + t];
        g_aggb[b * 64 + t] = s;
    }
}

// ==================== kernel 3: aggregate weights -> half2 pair layout ====
__global__ void aggw_kernel(const float* __restrict__ weight) {  // [4,64,64,3,3]
    const int idx = blockIdx.x * 256 + threadIdx.x;   // b*2048 + o*32 + p ; 32768 total
    const int b   = idx >> 11;
    const int rem = idx & 2047;
    const int o   = rem >> 5, p = rem & 31;
    const float a0 = g_att[b * 4 + 0], a1 = g_att[b * 4 + 1];
    const float a2 = g_att[b * 4 + 2], a3 = g_att[b * 4 + 3];
    const float* we = weight + (size_t)(o * 64 + 2 * p) * 9;   // even channel taps
    #pragma unroll
    for (int tap = 0; tap < 9; tap++) {
        float se = a0 * we[tap]
                 + a1 * we[36864 + tap]
                 + a2 * we[73728 + tap]
                 + a3 * we[110592 + tap];
        float so = a0 * we[9 + tap]
                 + a1 * we[36864 + 9 + tap]
                 + a2 * we[73728 + 9 + tap]
                 + a3 * we[110592 + 9 + tap];
        g_wh[(((b * 9 + tap) * 32) + p) * 64 + o] = pack_h2(se, so);
    }
}

// ==================== kernel 4: conv, fp16 m16n8k16, 9 tap-steps ====
// CTA = (y, b): m = 256 x-positions, n = 64. 128 threads / 4 warps, warp 64x64.
// s_A double [2][32 pair-rows][A_STRP u32]: interior gx at col gx+4, halo 3/260.
//   One buffer = ALL 64 channels of one input row; restaged per dy (2x), into
//   the idle buffer, committed as its own cp.async group.
// s_B double [2][32 pair-rows][B_STRP u32]: one tap's weights, straight copy.
#define A_STRP 264
#define B_STRP 72
#define SMEM_U32 (2 * 32 * A_STRP + 2 * 32 * B_STRP + 64)

__global__ __launch_bounds__(128, 2)
void conv_kernel(float* __restrict__ out) {
    extern __shared__ unsigned smem[];
    unsigned* s_A   = smem;                          // 2 * 32*264
    unsigned* s_B   = smem + 2 * 32 * A_STRP;        // 2 * 32*72
    float*   s_bias = (float*)(s_B + 2 * 32 * B_STRP);

    const int y    = blockIdx.x;
    const int b    = blockIdx.y;
    const int t    = threadIdx.x;
    const int lane = t & 31, w = t >> 5;
    const int g    = lane >> 2, tig = lane & 3;

    if (t < 64) s_bias[t] = g_aggb[b * 64 + t];

    float acc[4][8][4];
    #pragma unroll
    for (int mt = 0; mt < 4; mt++)
        #pragma unroll
        for (int nt = 0; nt < 8; nt++)
            #pragma unroll
            for (int r = 0; r < 4; r++) acc[mt][nt][r] = 0.f;

    const uint32_t sA_addr = smem_u32p(s_A);
    const uint32_t sB_addr = smem_u32p(s_B);

    // ---- A stage for dy group dyi (all 64 channels of row y+dyi-1) ----
    auto issueA = [&](int dyi) {
        const int gy  = y + dyi - 1;
        const bool oky = (unsigned)gy < 256u;
        const int gyc = oky ? gy : 0;
        const uint32_t sz = oky ? 16u : 0u;
        const uint32_t dstA = sA_addr + (uint32_t)((dyi & 1) * 32 * A_STRP * 4);
        const unsigned* srcb = g_xh + (((size_t)b * 32) << 16) + (size_t)gyc * 256;
        #pragma unroll
        for (int j = 0; j < 16; j++) {
            const int i  = j * 128 + t;              // 0..2047 chunks of 16B
            const int rr = i >> 6, k16 = i & 63;
            cp_async16z(dstA + (uint32_t)(rr * (A_STRP * 4) + 16 + k16 * 16),
                        srcb + (((size_t)rr) << 16) + k16 * 4, sz);
        }
        if (t < 64) {                                // halo pairs (1 u32 each side)
            const int rr = t >> 1, side = t & 1;
            const int gx = side ? 256 : -1;
            const bool okh = oky && (unsigned)gx < 256u;
            cp_async4z(dstA + (uint32_t)((rr * A_STRP + (side ? 260 : 3)) * 4),
                       g_xh + (((size_t)(b * 32 + rr)) << 16) + (size_t)gyc * 256 + (okh ? gx : 0),
                       okh ? 4u : 0u);
        }
    };

    // ---- B stage for tap: 32 pair-rows x 64 o, contiguous copy ----
    auto issueB = [&](int tap) {
        const unsigned* src = g_wh + (size_t)(b * 9 + tap) * 2048;
        const uint32_t dstb = sB_addr + (uint32_t)((tap & 1) * 32 * B_STRP * 4);
        #pragma unroll
        for (int j = 0; j < 4; j++) {
            const int i = j * 128 + t;               // 0..511 chunks of 16B
            const int rB = i >> 4, c4 = i & 15;
            cp_async16(dstb + (uint32_t)(rB * (B_STRP * 4) + c4 * 16), src + i * 4);
        }
    };

    // prologue
    issueA(0);
    issueB(0);
    CP_COMMIT();

    #pragma unroll 1
    for (int s = 0; s < 9; s++) {
        const int dyi = s / 3;
        const int dxi = s - dyi * 3;
        const int dx  = dxi - 1;

        // A(dyi+1) may lag only while another burst remains before it's needed
        if (dxi == 1 && dyi < 2) CP_WAIT1(); else CP_WAIT0();
        __syncthreads();

        if (s < 8) {
            issueB(s + 1);
            CP_COMMIT();
            if (dxi == 0 && dyi < 2) {
                issueA(dyi + 1);
                CP_COMMIT();
            }
        }

        const unsigned* sAb = s_A + (dyi & 1) * (32 * A_STRP);
        const unsigned* sBb = s_B + (s & 1) * (32 * B_STRP);
        const int colbase = w * 64 + g + dx + 4;

        #pragma unroll
        for (int ks = 0; ks < 4; ks++) {
            const int r0 = ks * 8 + tig, r1 = r0 + 4;
            uint32_t bf[8][2];
            #pragma unroll
            for (int nt = 0; nt < 8; nt++) {
                bf[nt][0] = sBb[r0 * B_STRP + nt * 8 + g];
                bf[nt][1] = sBb[r1 * B_STRP + nt * 8 + g];
            }
            const unsigned* aR0 = sAb + r0 * A_STRP + colbase;
            const unsigned* aR1 = sAb + r1 * A_STRP + colbase;
            #pragma unroll
            for (int mt = 0; mt < 4; mt++) {
                const uint32_t a0 = aR0[mt * 16];
                const uint32_t a1 = aR0[mt * 16 + 8];
                const uint32_t a2 = aR1[mt * 16];
                const uint32_t a3 = aR1[mt * 16 + 8];
                #pragma unroll
                for (int nt = 0; nt < 8; nt++)
                    mma_f16(acc[mt][nt][0], acc[mt][nt][1], acc[mt][nt][2], acc[mt][nt][3],
                            a0, a1, a2, a3, bf[nt][0], bf[nt][1]);
            }
        }
    }

    // ---- epilogue ----
    const size_t obase = ((size_t)b << 22) + (size_t)y * 256;
    #pragma unroll
    for (int nt = 0; nt < 8; nt++) {
        const int o0 = nt * 8 + 2 * tig;
        const float bias0 = s_bias[o0], bias1 = s_bias[o0 + 1];
        #pragma unroll
        for (int mt = 0; mt < 4; mt++) {
            const int m = w * 64 + mt * 16 + g;
            float* p0 = out + obase + ((size_t)o0 << 16) + m;
            float* p1 = out + obase + ((size_t)(o0 + 1) << 16) + m;
            p0[0] = acc[mt][nt][0] + bias0;
            p1[0] = acc[mt][nt][1] + bias1;
            p0[8] = acc[mt][nt][2] + bias0;
            p1[8] = acc[mt][nt][3] + bias1;
        }
    }
}

// ==================== launcher ====================
extern "C" void kernel_launch(void* const* d_in, const int* in_sizes, int n_in,
                              void* d_out, int out_size) {
    const float* x      = (const float*)d_in[0];  // [16,64,256,256]
    const float* fc1_w  = (const float*)d_in[1];  // [17,64]
    const float* fc2_w  = (const float*)d_in[2];  // [4,17]
    const float* fc2_b  = (const float*)d_in[3];  // [4]
    const float* weight = (const float*)d_in[4];  // [4,64,64,3,3]
    const float* bias_k = (const float*)d_in[5];  // [4,64]
    float* out = (float*)d_out;

    const int smem_bytes = SMEM_U32 * 4;
    cudaFuncSetAttribute(conv_kernel, cudaFuncAttributeMaxDynamicSharedMemorySize, smem_bytes);

    convert_pool_kernel<<<512, 256>>>(x);
    attn_kernel<<<16, 64>>>(fc1_w, fc2_w, fc2_b, bias_k);
    aggw_kernel<<<128, 256>>>(weight);
    conv_kernel<<<dim3(256, 16), 128, smem_bytes>>>(out);
}